// round 8
// baseline (speedup 1.0000x reference)
#include <cuda_runtime.h>
#include <cuda_bf16.h>
#include <cstdint>

// ---------------- problem constants ----------------
#define BB 16
#define QQ 100
#define TT 50
#define GG 16384
#define LL 21
#define KSPLIT 9                 // grid = 16*9 = 144 CTAs (~1 wave on 148 SMs)
#define KC 64                    // K per stage (64 bf16 = 128B row)
#define TOTSTAGE (GG / KC)       // 256 stages per batch, split 29/29/29/29/28*5
#define NTHREADS 512

// per-stage smem tile offsets (bytes)
#define OFF_AM 0                 // 128 rows x 128B bf16 (mask logits)
#define OFF_AS 16384             // 128 rows x 128B bf16 (sigmoid)
#define OFF_Y  32768             // 64 rows x 128B bf16 (targets)
#define STAGE_BYTES 40960
#define SMEM_DYN (2 * STAGE_BYTES)   // 81920

// ---------------- device scratch: per-ks slices, fully overwritten ----------------
__device__ float g_Dm[KSPLIT * BB * QQ * TT];
__device__ float g_Ds[KSPLIT * BB * QQ * TT];
__device__ float g_Ssp[KSPLIT * BB * QQ];
__device__ float g_Ssg[KSPLIT * BB * QQ];
__device__ float g_Sy[KSPLIT * BB * TT];

// ---------------- helpers ----------------
__device__ __forceinline__ uint32_t smem_u32(const void* p) {
    uint32_t a;
    asm("{ .reg .u64 t; cvta.to.shared.u64 t, %1; cvt.u32.u64 %0, t; }"
        : "=r"(a) : "l"(p));
    return a;
}
__device__ __forceinline__ uint32_t swz128(uint32_t off) {
    return off ^ ((off >> 3) & 0x70u);
}
__device__ __forceinline__ uint32_t lds32(uint32_t addr) {
    uint32_t v;
    asm volatile("ld.shared.b32 %0, [%1];" : "=r"(v) : "r"(addr));
    return v;
}
// softplus + sigmoid with 2 MUFU: tanh + lg2
//   h = tanh(v/2); sg = 0.5 + 0.5h; sigmoid(-v) = 0.5 - 0.5h
//   sp(v) = -ln(sigmoid(-v))
__device__ __forceinline__ void act(float v, float& sp, float& sg) {
    float h;
    asm("tanh.approx.f32 %0, %1;" : "=f"(h) : "f"(0.5f * v));
    float sgn = fmaf(-0.5f, h, 0.5f);
    sg = fmaf(0.5f, h, 0.5f);
    sgn = fmaxf(sgn, 1e-30f);
    float lg;
    asm("lg2.approx.f32 %0, %1;" : "=f"(lg) : "f"(sgn));
    sp = -0.6931471805599453f * lg;
}
__device__ __forceinline__ float red8(float v) {
#pragma unroll
    for (int d = 4; d; d >>= 1) v += __shfl_down_sync(0xFFFFFFFFu, v, d);
    return v;
}

// ---------------- main: activations + split-K HMMA GEMMs ----------------
__global__ void __launch_bounds__(NTHREADS, 1)
matcher_main(const float* __restrict__ m, const float* __restrict__ y) {
    extern __shared__ char smem[];
    uint32_t sb = smem_u32(smem);
    int tid = threadIdx.x;
    int wid = tid >> 5;
    int lid = tid & 31;
    int b = blockIdx.x / KSPLIT;
    int ks = blockIdx.x % KSPLIT;
    int nst = 28 + (ks < 4 ? 1 : 0);
    int s0 = 28 * ks + (ks < 4 ? ks : 4);
    int g0 = s0 * KC;

    // zero both stage buffers once (pad rows A[100:112), Y[50:56) must be 0)
    {
        uint4 z = make_uint4(0u, 0u, 0u, 0u);
        for (int i = tid; i < SMEM_DYN / 16; i += NTHREADS)
            reinterpret_cast<uint4*>(smem)[i] = z;
    }
    __syncthreads();

    // fill mapping: 8 threads/row, 8 floats each
    //   pass0: rows 0-63 (all threads);  pass1: rows 64-99 (tid<288, warps 0-8)
    //   y:     rows 0-49 (tid<400)
    int r0 = tid >> 3;
    int r1 = 64 + r0;
    int cb = (tid & 7) * 8;
    bool h1 = (tid < 288);
    bool hy = (tid < 400);
    const float* mrow0 = m + (size_t)(b * QQ + r0) * GG + g0 + cb;
    const float* mrow1 = m + (size_t)(b * QQ + (h1 ? r1 : 0)) * GG + g0 + cb;
    const float* yrow  = y + (size_t)(b * TT + (hy ? r0 : 0)) * GG + g0 + cb;
    uint32_t so  = swz128((uint32_t)(r0 * 128 + cb * 2));
    uint32_t so1 = swz128((uint32_t)(r1 * 128 + cb * 2));

    float sp0 = 0.f, sg0 = 0.f, sp1 = 0.f, sg1 = 0.f, syp = 0.f;
    float f0[8], f1[8], fy[8];

    auto loadG = [&](int it) {
        int gk = it * KC;
        float4 u0 = *(const float4*)(mrow0 + gk);
        float4 u1 = *(const float4*)(mrow0 + gk + 4);
        f0[0] = u0.x; f0[1] = u0.y; f0[2] = u0.z; f0[3] = u0.w;
        f0[4] = u1.x; f0[5] = u1.y; f0[6] = u1.z; f0[7] = u1.w;
        if (h1) {
            float4 v0 = *(const float4*)(mrow1 + gk);
            float4 v1 = *(const float4*)(mrow1 + gk + 4);
            f1[0] = v0.x; f1[1] = v0.y; f1[2] = v0.z; f1[3] = v0.w;
            f1[4] = v1.x; f1[5] = v1.y; f1[6] = v1.z; f1[7] = v1.w;
        }
        if (hy) {
            float4 w0 = *(const float4*)(yrow + gk);
            float4 w1 = *(const float4*)(yrow + gk + 4);
            fy[0] = w0.x; fy[1] = w0.y; fy[2] = w0.z; fy[3] = w0.w;
            fy[4] = w1.x; fy[5] = w1.y; fy[6] = w1.z; fy[7] = w1.w;
        }
    };

    auto storeS = [&](int buf) {
        char* stg = smem + buf * STAGE_BYTES;
        uint32_t pm[4], ps[4];
#pragma unroll
        for (int i = 0; i < 4; ++i) {
            float sa, ga, sc, gc;
            act(f0[2 * i], sa, ga);
            act(f0[2 * i + 1], sc, gc);
            sp0 += sa + sc; sg0 += ga + gc;
            __nv_bfloat162 hm = __floats2bfloat162_rn(f0[2 * i], f0[2 * i + 1]);
            __nv_bfloat162 hs = __floats2bfloat162_rn(ga, gc);
            pm[i] = *reinterpret_cast<uint32_t*>(&hm);
            ps[i] = *reinterpret_cast<uint32_t*>(&hs);
        }
        *(uint4*)(stg + OFF_AM + so) = make_uint4(pm[0], pm[1], pm[2], pm[3]);
        *(uint4*)(stg + OFF_AS + so) = make_uint4(ps[0], ps[1], ps[2], ps[3]);
        if (h1) {
#pragma unroll
            for (int i = 0; i < 4; ++i) {
                float sa, ga, sc, gc;
                act(f1[2 * i], sa, ga);
                act(f1[2 * i + 1], sc, gc);
                sp1 += sa + sc; sg1 += ga + gc;
                __nv_bfloat162 hm = __floats2bfloat162_rn(f1[2 * i], f1[2 * i + 1]);
                __nv_bfloat162 hs = __floats2bfloat162_rn(ga, gc);
                pm[i] = *reinterpret_cast<uint32_t*>(&hm);
                ps[i] = *reinterpret_cast<uint32_t*>(&hs);
            }
            *(uint4*)(stg + OFF_AM + so1) = make_uint4(pm[0], pm[1], pm[2], pm[3]);
            *(uint4*)(stg + OFF_AS + so1) = make_uint4(ps[0], ps[1], ps[2], ps[3]);
        }
        if (hy) {
            uint32_t py[4];
#pragma unroll
            for (int i = 0; i < 4; ++i) {
                syp += fy[2 * i] + fy[2 * i + 1];
                __nv_bfloat162 h2 = __floats2bfloat162_rn(fy[2 * i], fy[2 * i + 1]);
                py[i] = *reinterpret_cast<uint32_t*>(&h2);
            }
            *(uint4*)(stg + OFF_Y + so) = make_uint4(py[0], py[1], py[2], py[3]);
        }
    };

    // consumer warps 9-15: strip mt computes BOTH Dm and Ds (Y frag reuse)
    const bool cw = (wid >= 9);
    const int mt = wid - 9;           // 0..6
    const int gq = lid >> 2;          // 0..7
    const int tig = lid & 3;          // 0..3
    float accM[7][4], accS[7][4];
#pragma unroll
    for (int nt = 0; nt < 7; ++nt)
#pragma unroll
        for (int i = 0; i < 4; ++i) { accM[nt][i] = 0.0f; accS[nt][i] = 0.0f; }

    auto mmaStage = [&](int buf) {
        uint32_t base = sb + (uint32_t)(buf * STAGE_BYTES);
        uint32_t amb = base + OFF_AM;
        uint32_t asb = base + OFF_AS;
        uint32_t ybv = base + OFF_Y;
        uint32_t rlo = (uint32_t)((mt * 16 + gq) * 128);
        uint32_t rhi = rlo + 8 * 128;
#pragma unroll
        for (int kc = 0; kc < 4; ++kc) {
            uint32_t co = (uint32_t)(kc * 32 + tig * 4);
            uint32_t a0 = lds32(amb + swz128(rlo + co));
            uint32_t a1 = lds32(amb + swz128(rhi + co));
            uint32_t a2 = lds32(amb + swz128(rlo + co + 16));
            uint32_t a3 = lds32(amb + swz128(rhi + co + 16));
            uint32_t c0 = lds32(asb + swz128(rlo + co));
            uint32_t c1 = lds32(asb + swz128(rhi + co));
            uint32_t c2 = lds32(asb + swz128(rlo + co + 16));
            uint32_t c3 = lds32(asb + swz128(rhi + co + 16));
#pragma unroll
            for (int nt = 0; nt < 7; ++nt) {
                uint32_t yr = (uint32_t)((nt * 8 + gq) * 128);
                uint32_t b0 = lds32(ybv + swz128(yr + co));
                uint32_t b1 = lds32(ybv + swz128(yr + co + 16));
                asm volatile(
                    "mma.sync.aligned.m16n8k16.row.col.f32.bf16.bf16.f32 "
                    "{%0,%1,%2,%3}, {%4,%5,%6,%7}, {%8,%9}, {%0,%1,%2,%3};"
                    : "+f"(accM[nt][0]), "+f"(accM[nt][1]),
                      "+f"(accM[nt][2]), "+f"(accM[nt][3])
                    : "r"(a0), "r"(a1), "r"(a2), "r"(a3), "r"(b0), "r"(b1));
                asm volatile(
                    "mma.sync.aligned.m16n8k16.row.col.f32.bf16.bf16.f32 "
                    "{%0,%1,%2,%3}, {%4,%5,%6,%7}, {%8,%9}, {%0,%1,%2,%3};"
                    : "+f"(accS[nt][0]), "+f"(accS[nt][1]),
                      "+f"(accS[nt][2]), "+f"(accS[nt][3])
                    : "r"(c0), "r"(c1), "r"(c2), "r"(c3), "r"(b0), "r"(b1));
            }
        }
    };

    // pipeline: loadG(it+1) | consumers: mma(it) | storeS(it+1) | barrier
    loadG(0);
    storeS(0);
    __syncthreads();
#pragma unroll 1
    for (int it = 0; it < nst; ++it) {
        bool more = (it + 1 < nst);
        if (more) loadG(it + 1);
        if (cw) mmaStage(it & 1);
        if (more) storeS((it + 1) & 1);
        __syncthreads();
    }

    // ---- row-sum slice stores (unique writer per entry, no atomics) ----
    sp0 = red8(sp0); sg0 = red8(sg0);
    sp1 = red8(sp1); sg1 = red8(sg1);
    syp = red8(syp);
    int sl = ks * BB + b;
    if ((tid & 7) == 0) {
        g_Ssp[sl * QQ + r0] = sp0;
        g_Ssg[sl * QQ + r0] = sg0;
        if (h1) {
            g_Ssp[sl * QQ + r1] = sp1;
            g_Ssg[sl * QQ + r1] = sg1;
        }
        if (hy) g_Sy[sl * TT + r0] = syp;
    }

    // ---- D slice stores (unique writer per entry, no atomics) ----
    if (cw) {
        int rl = mt * 16 + gq;
        int rh = rl + 8;
        size_t sbase = (size_t)sl * QQ * TT;
#pragma unroll
        for (int nt = 0; nt < 7; ++nt) {
            int ca = nt * 8 + tig * 2;
            int cbn = ca + 1;
            if (rl < QQ) {
                if (ca < TT) {
                    g_Dm[sbase + rl * TT + ca] = accM[nt][0];
                    g_Ds[sbase + rl * TT + ca] = accS[nt][0];
                }
                if (cbn < TT) {
                    g_Dm[sbase + rl * TT + cbn] = accM[nt][1];
                    g_Ds[sbase + rl * TT + cbn] = accS[nt][1];
                }
            }
            if (rh < QQ) {
                if (ca < TT) {
                    g_Dm[sbase + rh * TT + ca] = accM[nt][2];
                    g_Ds[sbase + rh * TT + ca] = accS[nt][2];
                }
                if (cbn < TT) {
                    g_Dm[sbase + rh * TT + cbn] = accM[nt][3];
                    g_Ds[sbase + rh * TT + cbn] = accS[nt][3];
                }
            }
        }
    }
}

// ---------------- epilogue: sum slices + class softmax + combine ----------------
__global__ void matcher_epi(const float* __restrict__ cl,
                            const int* __restrict__ lab32,
                            float* __restrict__ out) {
    int b = blockIdx.x;
    int q = threadIdx.x;
    __shared__ float ssy[TT];
    __shared__ int s_i64;
    if (q == 0) {
        int ok = 1;
        for (int k = 0; k < 64; ++k) {
            int lo = lab32[2 * k], hi = lab32[2 * k + 1];
            if (hi != 0 || lo < 0 || lo >= LL) { ok = 0; break; }
        }
        s_i64 = ok;
    }
    if (q < TT) {
        float s = 0.0f;
        for (int ks = 0; ks < KSPLIT; ++ks)
            s += g_Sy[(ks * BB + b) * TT + q];
        ssy[q] = s;
    }
    __syncthreads();
    if (q >= QQ) return;

    const float* c = cl + (size_t)(b * QQ + q) * LL;
    float mx = -1e30f;
#pragma unroll
    for (int l = 0; l < LL; ++l) mx = fmaxf(mx, c[l]);
    float s = 0.0f;
#pragma unroll
    for (int l = 0; l < LL; ++l) s += __expf(c[l] - mx);
    float inv = 1.0f / s;

    float ssp = 0.0f, ssg = 0.0f;
    float dm_a[TT], ds_a[TT];
#pragma unroll
    for (int t = 0; t < TT; ++t) { dm_a[t] = 0.0f; ds_a[t] = 0.0f; }
    for (int ks = 0; ks < KSPLIT; ++ks) {
        int sl = ks * BB + b;
        ssp += g_Ssp[sl * QQ + q];
        ssg += g_Ssg[sl * QQ + q];
        const float2* pm = reinterpret_cast<const float2*>(&g_Dm[((size_t)sl * QQ + q) * TT]);
        const float2* ps = reinterpret_cast<const float2*>(&g_Ds[((size_t)sl * QQ + q) * TT]);
#pragma unroll
        for (int t2 = 0; t2 < TT / 2; ++t2) {
            float2 vm = pm[t2], vs = ps[t2];
            dm_a[2 * t2] += vm.x; dm_a[2 * t2 + 1] += vm.y;
            ds_a[2 * t2] += vs.x; ds_a[2 * t2 + 1] += vs.y;
        }
    }

    const float invG = 1.0f / (float)GG;
    int i64 = s_i64;
    for (int t = 0; t < TT; ++t) {
        int idx = b * TT + t;
        int lbl = i64 ? lab32[2 * idx] : lab32[idx];
        float p = __expf(c[lbl] - mx) * inv;
        float dice = 1.0f - (2.0f * ds_a[t] + 1.0f) / (ssg + ssy[t] + 1.0f);
        float cost = (ssp - dm_a[t]) * invG - p + dice;
        out[(b * QQ + q) * TT + t] = cost;
    }
}

// ---------------- launch ----------------
extern "C" void kernel_launch(void* const* d_in, const int* in_sizes, int n_in,
                              void* d_out, int out_size) {
    (void)in_sizes; (void)n_in; (void)out_size;
    const float* m = (const float*)d_in[0];
    const float* cl = (const float*)d_in[1];
    const float* y = (const float*)d_in[2];
    const int* lab = (const int*)d_in[3];
    float* out = (float*)d_out;

    cudaFuncSetAttribute(matcher_main,
                         cudaFuncAttributeMaxDynamicSharedMemorySize, SMEM_DYN);

    matcher_main<<<BB * KSPLIT, NTHREADS, SMEM_DYN>>>(m, y);
    matcher_epi<<<BB, 128>>>(cl, lab, out);
}

// round 9
// speedup vs baseline: 1.5572x; 1.5572x over previous
#include <cuda_runtime.h>
#include <cuda_bf16.h>
#include <cstdint>

// ---------------- problem constants ----------------
#define BB 16
#define QQ 100
#define TT 50
#define GG 16384
#define LL 21
#define KSPLIT 9                 // grid = 16*9 = 144 CTAs (~1 wave on 148 SMs)
#define KC 64                    // K per stage (64 bf16 = 128B row)
#define NTHREADS 512

// per-stage smem tile offsets (bytes)
#define OFF_AM 0                 // 128 rows x 128B bf16 (mask logits)
#define OFF_AS 16384             // 128 rows x 128B bf16 (sigmoid)
#define OFF_Y  32768             // 64 rows x 128B bf16 (targets)
#define STAGE_BYTES 40960
#define SMEM_DYN (2 * STAGE_BYTES)   // 81920

// ---------------- device scratch: per-ks slices, fully overwritten ----------------
__device__ float g_Dm[KSPLIT * BB * QQ * TT];
__device__ float g_Ds[KSPLIT * BB * QQ * TT];
__device__ float g_Ssp[KSPLIT * BB * QQ];
__device__ float g_Ssg[KSPLIT * BB * QQ];
__device__ float g_Sy[KSPLIT * BB * TT];

// ---------------- helpers ----------------
__device__ __forceinline__ uint32_t smem_u32(const void* p) {
    uint32_t a;
    asm("{ .reg .u64 t; cvta.to.shared.u64 t, %1; cvt.u32.u64 %0, t; }"
        : "=r"(a) : "l"(p));
    return a;
}
__device__ __forceinline__ uint32_t swz128(uint32_t off) {
    return off ^ ((off >> 3) & 0x70u);
}
__device__ __forceinline__ uint32_t lds32(uint32_t addr) {
    uint32_t v;
    asm volatile("ld.shared.b32 %0, [%1];" : "=r"(v) : "r"(addr));
    return v;
}
// softplus + sigmoid with 2 MUFU: tanh + lg2
__device__ __forceinline__ void act(float v, float& sp, float& sg) {
    float h;
    asm("tanh.approx.f32 %0, %1;" : "=f"(h) : "f"(0.5f * v));
    float sgn = fmaf(-0.5f, h, 0.5f);
    sg = fmaf(0.5f, h, 0.5f);
    sgn = fmaxf(sgn, 1e-30f);
    float lg;
    asm("lg2.approx.f32 %0, %1;" : "=f"(lg) : "f"(sgn));
    sp = -0.6931471805599453f * lg;
}
__device__ __forceinline__ float red8(float v) {
#pragma unroll
    for (int d = 4; d; d >>= 1) v += __shfl_down_sync(0xFFFFFFFFu, v, d);
    return v;
}

// ---------------- main: activations + split-K HMMA GEMMs ----------------
__global__ void __launch_bounds__(NTHREADS, 1)
matcher_main(const float* __restrict__ m, const float* __restrict__ y) {
    extern __shared__ char smem[];
    uint32_t sb = smem_u32(smem);
    int tid = threadIdx.x;
    int wid = tid >> 5;
    int lid = tid & 31;
    int b = blockIdx.x / KSPLIT;
    int ks = blockIdx.x % KSPLIT;
    int nst = 28 + (ks < 4 ? 1 : 0);
    int s0 = 28 * ks + (ks < 4 ? ks : 4);
    int g0 = s0 * KC;

    // zero both stage buffers once (pad rows A[100:112), Y[50:56) must be 0)
    {
        uint4 z = make_uint4(0u, 0u, 0u, 0u);
        for (int i = tid; i < SMEM_DYN / 16; i += NTHREADS)
            reinterpret_cast<uint4*>(smem)[i] = z;
    }
    __syncthreads();

    // fill mapping: 8 threads/row, 8 floats each
    int r0 = tid >> 3;
    int r1 = 64 + r0;
    int cb = (tid & 7) * 8;
    bool h1 = (tid < 288);
    bool hy = (tid < 400);
    const float* mrow0 = m + (size_t)(b * QQ + r0) * GG + g0 + cb;
    const float* mrow1 = m + (size_t)(b * QQ + (h1 ? r1 : 0)) * GG + g0 + cb;
    const float* yrow  = y + (size_t)(b * TT + (hy ? r0 : 0)) * GG + g0 + cb;
    uint32_t so  = swz128((uint32_t)(r0 * 128 + cb * 2));
    uint32_t so1 = swz128((uint32_t)(r1 * 128 + cb * 2));

    float sp0 = 0.f, sg0 = 0.f, sp1 = 0.f, sg1 = 0.f, syp = 0.f;
    float f0[8], f1[8], fy[8];

    auto loadG = [&](int it) {
        int gk = it * KC;
        float4 u0 = *(const float4*)(mrow0 + gk);
        float4 u1 = *(const float4*)(mrow0 + gk + 4);
        f0[0] = u0.x; f0[1] = u0.y; f0[2] = u0.z; f0[3] = u0.w;
        f0[4] = u1.x; f0[5] = u1.y; f0[6] = u1.z; f0[7] = u1.w;
        if (h1) {
            float4 v0 = *(const float4*)(mrow1 + gk);
            float4 v1 = *(const float4*)(mrow1 + gk + 4);
            f1[0] = v0.x; f1[1] = v0.y; f1[2] = v0.z; f1[3] = v0.w;
            f1[4] = v1.x; f1[5] = v1.y; f1[6] = v1.z; f1[7] = v1.w;
        }
        if (hy) {
            float4 w0 = *(const float4*)(yrow + gk);
            float4 w1 = *(const float4*)(yrow + gk + 4);
            fy[0] = w0.x; fy[1] = w0.y; fy[2] = w0.z; fy[3] = w0.w;
            fy[4] = w1.x; fy[5] = w1.y; fy[6] = w1.z; fy[7] = w1.w;
        }
    };

    auto storeS = [&](int buf) {
        char* stg = smem + buf * STAGE_BYTES;
        uint32_t pm[4], ps[4];
#pragma unroll
        for (int i = 0; i < 4; ++i) {
            float sa, ga, sc, gc;
            act(f0[2 * i], sa, ga);
            act(f0[2 * i + 1], sc, gc);
            sp0 += sa + sc; sg0 += ga + gc;
            __nv_bfloat162 hm = __floats2bfloat162_rn(f0[2 * i], f0[2 * i + 1]);
            __nv_bfloat162 hs = __floats2bfloat162_rn(ga, gc);
            pm[i] = *reinterpret_cast<uint32_t*>(&hm);
            ps[i] = *reinterpret_cast<uint32_t*>(&hs);
        }
        *(uint4*)(stg + OFF_AM + so) = make_uint4(pm[0], pm[1], pm[2], pm[3]);
        *(uint4*)(stg + OFF_AS + so) = make_uint4(ps[0], ps[1], ps[2], ps[3]);
        if (h1) {
#pragma unroll
            for (int i = 0; i < 4; ++i) {
                float sa, ga, sc, gc;
                act(f1[2 * i], sa, ga);
                act(f1[2 * i + 1], sc, gc);
                sp1 += sa + sc; sg1 += ga + gc;
                __nv_bfloat162 hm = __floats2bfloat162_rn(f1[2 * i], f1[2 * i + 1]);
                __nv_bfloat162 hs = __floats2bfloat162_rn(ga, gc);
                pm[i] = *reinterpret_cast<uint32_t*>(&hm);
                ps[i] = *reinterpret_cast<uint32_t*>(&hs);
            }
            *(uint4*)(stg + OFF_AM + so1) = make_uint4(pm[0], pm[1], pm[2], pm[3]);
            *(uint4*)(stg + OFF_AS + so1) = make_uint4(ps[0], ps[1], ps[2], ps[3]);
        }
        if (hy) {
            uint32_t py[4];
#pragma unroll
            for (int i = 0; i < 4; ++i) {
                syp += fy[2 * i] + fy[2 * i + 1];
                __nv_bfloat162 h2 = __floats2bfloat162_rn(fy[2 * i], fy[2 * i + 1]);
                py[i] = *reinterpret_cast<uint32_t*>(&h2);
            }
            *(uint4*)(stg + OFF_Y + so) = make_uint4(py[0], py[1], py[2], py[3]);
        }
    };

    // consumer warps 9-15: strip mt computes BOTH Dm and Ds (Y frag reuse)
    const bool cw = (wid >= 9);
    const int mt = wid - 9;           // 0..6
    const int gq = lid >> 2;          // 0..7
    const int tig = lid & 3;          // 0..3
    float accM[7][4], accS[7][4];
#pragma unroll
    for (int nt = 0; nt < 7; ++nt)
#pragma unroll
        for (int i = 0; i < 4; ++i) { accM[nt][i] = 0.0f; accS[nt][i] = 0.0f; }

    auto mmaStage = [&](int buf) {
        uint32_t base = sb + (uint32_t)(buf * STAGE_BYTES);
        uint32_t amb = base + OFF_AM;
        uint32_t asb = base + OFF_AS;
        uint32_t ybv = base + OFF_Y;
        uint32_t rlo = (uint32_t)((mt * 16 + gq) * 128);
        uint32_t rhi = rlo + 8 * 128;
#pragma unroll
        for (int kc = 0; kc < 4; ++kc) {
            uint32_t co = (uint32_t)(kc * 32 + tig * 4);
            uint32_t a0 = lds32(amb + swz128(rlo + co));
            uint32_t a1 = lds32(amb + swz128(rhi + co));
            uint32_t a2 = lds32(amb + swz128(rlo + co + 16));
            uint32_t a3 = lds32(amb + swz128(rhi + co + 16));
            uint32_t c0 = lds32(asb + swz128(rlo + co));
            uint32_t c1 = lds32(asb + swz128(rhi + co));
            uint32_t c2 = lds32(asb + swz128(rlo + co + 16));
            uint32_t c3 = lds32(asb + swz128(rhi + co + 16));
#pragma unroll
            for (int nt = 0; nt < 7; ++nt) {
                uint32_t yr = (uint32_t)((nt * 8 + gq) * 128);
                uint32_t b0 = lds32(ybv + swz128(yr + co));
                uint32_t b1 = lds32(ybv + swz128(yr + co + 16));
                asm volatile(
                    "mma.sync.aligned.m16n8k16.row.col.f32.bf16.bf16.f32 "
                    "{%0,%1,%2,%3}, {%4,%5,%6,%7}, {%8,%9}, {%0,%1,%2,%3};"
                    : "+f"(accM[nt][0]), "+f"(accM[nt][1]),
                      "+f"(accM[nt][2]), "+f"(accM[nt][3])
                    : "r"(a0), "r"(a1), "r"(a2), "r"(a3), "r"(b0), "r"(b1));
                asm volatile(
                    "mma.sync.aligned.m16n8k16.row.col.f32.bf16.bf16.f32 "
                    "{%0,%1,%2,%3}, {%4,%5,%6,%7}, {%8,%9}, {%0,%1,%2,%3};"
                    : "+f"(accS[nt][0]), "+f"(accS[nt][1]),
                      "+f"(accS[nt][2]), "+f"(accS[nt][3])
                    : "r"(c0), "r"(c1), "r"(c2), "r"(c3), "r"(b0), "r"(b1));
            }
        }
    };

    // pipeline
    loadG(0);
    storeS(0);
    __syncthreads();
#pragma unroll 1
    for (int it = 0; it < nst; ++it) {
        bool more = (it + 1 < nst);
        if (more) loadG(it + 1);
        if (cw) mmaStage(it & 1);
        if (more) storeS((it + 1) & 1);
        __syncthreads();
    }

    // ---- row-sum slice stores (unique writer per entry, no atomics) ----
    sp0 = red8(sp0); sg0 = red8(sg0);
    sp1 = red8(sp1); sg1 = red8(sg1);
    syp = red8(syp);
    int sl = ks * BB + b;
    if ((tid & 7) == 0) {
        g_Ssp[sl * QQ + r0] = sp0;
        g_Ssg[sl * QQ + r0] = sg0;
        if (h1) {
            g_Ssp[sl * QQ + r1] = sp1;
            g_Ssg[sl * QQ + r1] = sg1;
        }
        if (hy) g_Sy[sl * TT + r0] = syp;
    }

    // ---- D slice stores (unique writer per entry, no atomics) ----
    if (cw) {
        int rl = mt * 16 + gq;
        int rh = rl + 8;
        size_t sbase = (size_t)sl * QQ * TT;
#pragma unroll
        for (int nt = 0; nt < 7; ++nt) {
            int ca = nt * 8 + tig * 2;
            int cbn = ca + 1;
            if (rl < QQ) {
                if (ca < TT) {
                    g_Dm[sbase + rl * TT + ca] = accM[nt][0];
                    g_Ds[sbase + rl * TT + ca] = accS[nt][0];
                }
                if (cbn < TT) {
                    g_Dm[sbase + rl * TT + cbn] = accM[nt][1];
                    g_Ds[sbase + rl * TT + cbn] = accS[nt][1];
                }
            }
            if (rh < QQ) {
                if (ca < TT) {
                    g_Dm[sbase + rh * TT + ca] = accM[nt][2];
                    g_Ds[sbase + rh * TT + ca] = accS[nt][2];
                }
                if (cbn < TT) {
                    g_Dm[sbase + rh * TT + cbn] = accM[nt][3];
                    g_Ds[sbase + rh * TT + cbn] = accS[nt][3];
                }
            }
        }
    }
}

// ---------------- epilogue: one warp per (b,q) ----------------
__global__ void __launch_bounds__(128, 8)
matcher_epi(const float* __restrict__ cl,
            const int* __restrict__ lab32,
            float* __restrict__ out) {
    int warp = (blockIdx.x * blockDim.x + threadIdx.x) >> 5;
    int lane = threadIdx.x & 31;
    if (warp >= BB * QQ) return;
    int b = warp / QQ;
    int q = warp - b * QQ;

    // int64-vs-int32 label detection (warp-uniform, cached)
    int i64;
    {
        int ok = 1;
#pragma unroll
        for (int k = 0; k < 8; ++k) {
            int lo = lab32[2 * k], hi = lab32[2 * k + 1];
            if (hi != 0 || lo < 0 || lo >= LL) { ok = 0; break; }
        }
        i64 = ok;
    }

    // lane-parallel softmax over L=21
    const float* c = cl + (size_t)(b * QQ + q) * LL;
    float v = (lane < LL) ? c[lane] : -1e30f;
    float mx = v;
#pragma unroll
    for (int o = 16; o; o >>= 1) mx = fmaxf(mx, __shfl_xor_sync(0xFFFFFFFFu, mx, o));
    float e = (lane < LL) ? __expf(v - mx) : 0.0f;
    float s = e;
#pragma unroll
    for (int o = 16; o; o >>= 1) s += __shfl_xor_sync(0xFFFFFFFFu, s, o);
    float pl = e / s;    // lane l holds softmax prob of class l

    // warp-uniform row sums (broadcast loads)
    float ssp = 0.0f, ssg = 0.0f;
#pragma unroll
    for (int ks = 0; ks < KSPLIT; ++ks) {
        int sl = ks * BB + b;
        ssp += g_Ssp[sl * QQ + q];
        ssg += g_Ssg[sl * QQ + q];
    }

    const float invG = 1.0f / (float)GG;
    size_t rowoff = (size_t)(b * QQ + q) * TT;

#pragma unroll
    for (int half = 0; half < 2; ++half) {
        int t = lane + half * 32;
        if (t < TT) {
            float dm = 0.0f, ds = 0.0f, sy = 0.0f;
#pragma unroll
            for (int ks = 0; ks < KSPLIT; ++ks) {
                int sl = ks * BB + b;
                size_t off = (size_t)sl * QQ * TT + q * TT + t;
                dm += g_Dm[off];
                ds += g_Ds[off];
                sy += g_Sy[sl * TT + t];
            }
            int idx = b * TT + t;
            int lbl = i64 ? lab32[2 * idx] : lab32[idx];
            float p = __shfl_sync(0xFFFFFFFFu, pl, lbl);
            float dice = 1.0f - (2.0f * ds + 1.0f) / (ssg + sy + 1.0f);
            out[rowoff + t] = (ssp - dm) * invG - p + dice;
        } else {
            __shfl_sync(0xFFFFFFFFu, pl, 0);  // keep shfl convergent
        }
    }
}

// ---------------- launch ----------------
extern "C" void kernel_launch(void* const* d_in, const int* in_sizes, int n_in,
                              void* d_out, int out_size) {
    (void)in_sizes; (void)n_in; (void)out_size;
    const float* m = (const float*)d_in[0];
    const float* cl = (const float*)d_in[1];
    const float* y = (const float*)d_in[2];
    const int* lab = (const int*)d_in[3];
    float* out = (float*)d_out;

    cudaFuncSetAttribute(matcher_main,
                         cudaFuncAttributeMaxDynamicSharedMemorySize, SMEM_DYN);

    matcher_main<<<BB * KSPLIT, NTHREADS, SMEM_DYN>>>(m, y);
    // one warp per (b,q): 1600 warps -> 400 blocks x 128 threads
    matcher_epi<<<(BB * QQ + 3) / 4, 128>>>(cl, lab, out);
}